// round 14
// baseline (speedup 1.0000x reference)
#include <cuda_runtime.h>
#include <math.h>
#include <float.h>
#include <stdint.h>

#define Bb 4
#define Nn 8192
#define Ss 2048
#define Kk 64
#define EPSf 1e-5f

#define FCTAS 4                  // 1 FPS CTA per batch
#define WCTAS 144                // persistent worker CTAs
#define GRID  (FCTAS + WCTAS)    // 148 CTAs = 1/SM, single wave
#define TPB   512
#define NT    ((Bb*Ss)/4)        // worker tasks (4 centroids each)

typedef unsigned long long ull;

// ---------------- device scratch ----------------
__device__ float g_cen[Bb*Ss*3];
__device__ int   g_prog[Bb];
__device__ float g_sx[Bb*Nn];    // spatially sorted coords
__device__ float g_sy[Bb*Nn];
__device__ float g_sz[Bb*Nn];

// ---------------- packed f32x2 helpers (per-lane rn == scalar rn) ----------------
__device__ __forceinline__ ull pk2(float lo, float hi) {
    ull r; asm("mov.b64 %0, {%1, %2};" : "=l"(r) : "f"(lo), "f"(hi)); return r;
}
__device__ __forceinline__ void up2(ull v, float& a, float& b) {
    asm("mov.b64 {%0, %1}, %2;" : "=f"(a), "=f"(b) : "l"(v));
}
__device__ __forceinline__ ull add2(ull a, ull b) {
    ull r; asm("add.rn.f32x2 %0, %1, %2;" : "=l"(r) : "l"(a), "l"(b)); return r;
}
__device__ __forceinline__ ull mul2(ull a, ull b) {
    ull r; asm("mul.rn.f32x2 %0, %1, %2;" : "=l"(r) : "l"(a), "l"(b)); return r;
}

__device__ __forceinline__ int ld_acquire_gpu(const int* p) {
    int v; asm volatile("ld.acquire.gpu.global.s32 %0, [%1];" : "=r"(v) : "l"(p) : "memory");
    return v;
}
__device__ __forceinline__ void st_release_gpu(int* p, int v) {
    asm volatile("st.release.gpu.global.s32 [%0], %1;" :: "l"(p), "r"(v) : "memory");
}

// weight pointers, passed by value
struct WPtrs {
    const float *W1, *b1, *g1, *bt1, *m1, *v1;
    const float *W2, *b2, *g2, *bt2, *m2, *v2;
    const float *W3, *b3, *g3, *bt3, *m3, *v3;
};

// ---------------- spatial counting sort (Morton 8x8x8) + g_prog reset ----------------
__global__ void __launch_bounds__(1024) sort_kernel(const float* __restrict__ x)
{
    __shared__ int cnt[512];
    __shared__ int psum[512];
    const int b = blockIdx.x;
    const int tid = threadIdx.x;
    const float* xb = x + (size_t)b * Nn * 3;

    if (tid == 0) g_prog[b] = 0;
    if (tid < 512) cnt[tid] = 0;
    __syncthreads();

    int cid[8];
#pragma unroll
    for (int j = 0; j < 8; j++) {
        int p = tid * 8 + j;
        float px = xb[p*3 + 0], py = xb[p*3 + 1], pz = xb[p*3 + 2];
        int ix = min(7, max(0, (int)(px * 8.0f)));
        int iy = min(7, max(0, (int)(py * 8.0f)));
        int iz = min(7, max(0, (int)(pz * 8.0f)));
        int m = (ix & 1) | ((iy & 1) << 1) | ((iz & 1) << 2)
              | ((ix & 2) << 2) | ((iy & 2) << 3) | ((iz & 2) << 4)
              | ((ix & 4) << 4) | ((iy & 4) << 5) | ((iz & 4) << 6);
        cid[j] = m;
        atomicAdd(&cnt[m], 1);
    }
    __syncthreads();
    // Hillis-Steele exclusive scan over 512 counts
    if (tid < 512) psum[tid] = cnt[tid];
    __syncthreads();
    for (int off = 1; off < 512; off <<= 1) {
        int v = 0;
        if (tid < 512 && tid >= off) v = psum[tid - off];
        __syncthreads();
        if (tid < 512 && tid >= off) psum[tid] += v;
        __syncthreads();
    }
    if (tid < 512) { psum[tid] -= cnt[tid]; cnt[tid] = 0; }
    __syncthreads();
#pragma unroll
    for (int j = 0; j < 8; j++) {
        int p = tid * 8 + j;
        int pos = psum[cid[j]] + atomicAdd(&cnt[cid[j]], 1);
        g_sx[b*Nn + pos] = xb[p*3 + 0];
        g_sy[b*Nn + pos] = xb[p*3 + 1];
        g_sz[b*Nn + pos] = xb[p*3 + 2];
    }
}

// ---------------- shared-memory layout (floats) : worker view ----------------
#define OW1 0
#define OB1 (OW1 + 64*67)
#define OW2 (OB1 + 64)
#define OB2 (OW2 + 64*65)
#define OW3 (OB2 + 64)
#define OB3 (OW3 + 128*65)
#define OBUF (OB3 + 128)
#define GRP  (67*65 + 64*65)
#define OIDXA (OBUF + 4*GRP)
#define SMEM_FLOATS (OIDXA + 4*64)
#define SMEM_BYTES  (SMEM_FLOATS * 4)
// fps view (same dynamic buffer): sorted coords + stamped key slots
#define F_SX   0
#define F_SY   Nn
#define F_SZ   (2*Nn)
#define F_KEY  (3*Nn)            // [2][16] u64 stamped keys (parity-buffered)

// =====================================================================
// persistent kernel, single launch (512 threads everywhere):
//   CTA 0..3   : FPS, 512 thr x 16 pts, exact pruning, BARRIER-FREE combine
//   CTA 4..147 : workers (4 x 128-thread groups), consume via g_prog
// =====================================================================
__global__ void __launch_bounds__(TPB, 1)
pipe_kernel(const float* __restrict__ x, const float* __restrict__ xc,
            float* __restrict__ out, WPtrs w)
{
    extern __shared__ float sm[];
    const int tid  = threadIdx.x;
    const int lane = tid & 31;
    const int wrp  = tid >> 5;

    if (blockIdx.x < FCTAS) {
        // ================= FPS (512 threads, 16 sorted pts/thread) =================
        const int b = blockIdx.x;

        float* sxs = sm + F_SX;
        float* sys = sm + F_SY;
        float* szs = sm + F_SZ;
        volatile ull* skey = (volatile ull*)(sm + F_KEY);  // [2][16]

        for (int i = tid; i < Nn; i += TPB) {
            sxs[i] = g_sx[b*Nn + i];
            sys[i] = g_sy[b*Nn + i];
            szs[i] = g_sz[b*Nn + i];
        }
        // init both parity slot sets with an impossible stamp (s < 2048 always)
        if (tid < 32) ((ull*)(sm + F_KEY))[tid] = 0x7FFFFull;

        // 16 sorted points per thread (8 packed pairs); static reg indexing only
        ull px[8], py[8], pz[8];
        float dist[16];
#pragma unroll
        for (int i = 0; i < 8; i++) {
            int p = b*Nn + tid * 16 + i * 2;
            px[i] = pk2(g_sx[p], g_sx[p+1]);
            py[i] = pk2(g_sy[p], g_sy[p+1]);
            pz[i] = pk2(g_sz[p], g_sz[p+1]);
        }
#pragma unroll
        for (int j = 0; j < 16; j++) dist[j] = 1e10f;

        // per-thread bounding ball (m, rr) over its 16 points (conservative fp)
        float mx = 0.f, my = 0.f, mz = 0.f;
#pragma unroll
        for (int i = 0; i < 8; i++) {
            float a0, a1;
            up2(px[i], a0, a1); mx += a0 + a1;
            up2(py[i], a0, a1); my += a0 + a1;
            up2(pz[i], a0, a1); mz += a0 + a1;
        }
        mx *= 0.0625f; my *= 0.0625f; mz *= 0.0625f;
        float r2 = 0.f;
#pragma unroll
        for (int i = 0; i < 8; i++) {
            float a0, a1, b0, b1, c0, c1;
            up2(px[i], a0, a1); up2(py[i], b0, b1); up2(pz[i], c0, c1);
            float dx0 = a0 - mx, dy0 = b0 - my, dz0 = c0 - mz;
            float dx1 = a1 - mx, dy1 = b1 - my, dz1 = c1 - mz;
            r2 = fmaxf(r2, dx0*dx0 + dy0*dy0 + dz0*dz0);
            r2 = fmaxf(r2, dx1*dx1 + dy1*dy1 + dz1*dz1);
        }
        const float rr = __fsqrt_rn(r2) * 1.0002f + 1e-7f;

        float T  = 3.0e38f;      // prune threshold (forces full path initially)
        float bv = 0.f;          // cached per-thread max dist
        int   bj = 0;            // cached per-thread best local j (0..15)

        // initial centroid = ORIGINAL point 0's coords
        const float* xb0 = x + (size_t)b * Nn * 3;
        float cx = xb0[0], cy = xb0[1], cz = xb0[2];

        int* progp = &g_prog[b];
        __syncthreads();   // staging + slot init done (only barrier in FPS)

        for (int s = 0; s < Ss; s++) {
            const int par = s & 1;
            if (tid == 0) {
                int oc = (b*Ss + s) * 3;
                g_cen[oc+0] = cx; g_cen[oc+1] = cy; g_cen[oc+2] = cz;
                out[oc+0]  = cx; out[oc+1]  = cy; out[oc+2]  = cz;
                if ((s & 7) == 7) st_release_gpu(progp, s + 1);
            }

            // exact prune: |c-m| >= rr + sqrt(bv) (with margins) -> no update possible
            float ex = cx - mx, ey = cy - my, ez = cz - mz;
            float s2 = fmaf(ez, ez, fmaf(ey, ey, ex*ex));
            bool fullp = s2 < T;
            if (__any_sync(0xffffffffu, fullp)) {
                if (fullp) {
                    const ull ncx = pk2(-cx, -cx);
                    const ull ncy = pk2(-cy, -cy);
                    const ull ncz = pk2(-cz, -cz);
                    float nbv = -1.0f;
                    int   nbj = 0;
#pragma unroll
                    for (int i = 0; i < 8; i++) {
                        ull dx = add2(px[i], ncx);
                        ull dy = add2(py[i], ncy);
                        ull dz = add2(pz[i], ncz);
                        ull dd = add2(add2(mul2(dx,dx), mul2(dy,dy)), mul2(dz,dz));
                        float d0, d1; up2(dd, d0, d1);
                        float n0 = fminf(dist[2*i],   d0);
                        float n1 = fminf(dist[2*i+1], d1);
                        dist[2*i] = n0; dist[2*i+1] = n1;
                        float vp = fmaxf(n0, n1);
                        int   jp = (n0 >= n1) ? (2*i) : (2*i + 1);  // tie -> lower j
                        if (vp > nbv) { nbv = vp; nbj = jp; }       // strict > keeps lower j
                    }
                    bv = nbv; bj = nbj;
                    float sq = __fsqrt_rn(bv) * 1.0001f;
                    float t0 = (rr + sq) * 1.0001f;
                    T = t0 * t0;
                }
            }

            // warp combine: max value, then min sorted index on ties
            unsigned mv   = __float_as_uint(bv);
            unsigned wmax = __reduce_max_sync(0xffffffffu, mv);
            unsigned cand = (mv == wmax) ? (unsigned)(tid*16 + bj) : 0xffffffffu;
            unsigned wmi  = __reduce_min_sync(0xffffffffu, cand);

            // publish stamped key: {distbits[63:32] | ~idx13[31:19] | step[18:0]}
            // single aligned 64-bit volatile store = atomic; stamp rides in-word.
            if (lane == 0)
                skey[par*16 + wrp] = ((ull)wmax << 32)
                                   | ((ull)((~wmi) & 0x1FFFu) << 19)
                                   | (ull)(unsigned)s;

            // barrier-free: poll until all 16 slots carry stamp s
            ull k = 0;
            for (;;) {
                if (lane < 16) k = skey[par*16 + lane];
                unsigned ok = __ballot_sync(0xffffffffu,
                    (lane >= 16) || (((unsigned)k & 0x7FFFFu) == (unsigned)s));
                if (ok == 0xffffffffu) break;
            }

            // block combine: max distbits, then max ~idx (= min idx) on ties
            unsigned hi = (unsigned)(k >> 32);
            unsigned lo = (unsigned)k;
            unsigned M  = __reduce_max_sync(0xffffffffu, (lane < 16) ? hi : 0u);
            unsigned c2 = (lane < 16 && hi == M) ? lo : 0u;
            unsigned L  = __reduce_max_sync(0xffffffffu, c2);
            int cur = (int)((~(L >> 19)) & 0x1FFFu);   // sorted index
            cx = sxs[cur]; cy = sys[cur]; cz = szs[cur];
        }
        return;
    }

    // ================= persistent worker: ball query + MLP (512 thr) =================
    const int widx_ = blockIdx.x - FCTAS;

    // stage FOLDED weights, computed directly from raw inputs
    for (int i = tid; i < 64*67; i += TPB) {
        int o = i / 67;
        sm[OW1 + i] = w.W1[i] * (w.g1[o] * rsqrtf(w.v1[o] + EPSf));
    }
    for (int i = tid; i < 64*64; i += TPB) {
        int o = i >> 6, c = i & 63;
        sm[OW2 + o*65 + c] = w.W2[i] * (w.g2[o] * rsqrtf(w.v2[o] + EPSf));
    }
    for (int i = tid; i < 128*64; i += TPB) {
        int o = i >> 6, c = i & 63;
        sm[OW3 + o*65 + c] = w.W3[i] * (w.g3[o] * rsqrtf(w.v3[o] + EPSf));
    }
    for (int i = tid; i < 64; i += TPB) {
        sm[OB1 + i] = (w.b1[i] - w.m1[i]) * (w.g1[i] * rsqrtf(w.v1[i] + EPSf)) + w.bt1[i];
        sm[OB2 + i] = (w.b2[i] - w.m2[i]) * (w.g2[i] * rsqrtf(w.v2[i] + EPSf)) + w.bt2[i];
    }
    for (int i = tid; i < 128; i += TPB)
        sm[OB3 + i] = (w.b3[i] - w.m3[i]) * (w.g3[i] * rsqrtf(w.v3[i] + EPSf)) + w.bt3[i];

    float* pooled = out + (size_t)Bb * Ss * 3;

    // 4 warpgroups of 128 threads; one centroid per group
    const int wgid    = tid >> 7;        // 0..3
    const int wg_tid  = tid & 127;
    const int tx      = wg_tid & 15;     // 4 k-cols each
    const int ty      = wg_tid >> 4;     // 8 out-rows each (0..7)
    const int wg_warp = (tid >> 5) & 3;

    for (int t = widx_; t < NT; t += WCTAS) {
        const int b  = t & 3;
        const int s0 = (t >> 2) * 4;

        if (tid == 0) {
            while (ld_acquire_gpu(&g_prog[b]) < s0 + 4) __nanosleep(128);
        }
        __syncthreads();   // progress visible + previous task's buffers free

        // ---- ball query: warps 0..3, one centroid each ----
        if (wrp < 4) {
            const int cen = b * Ss + s0 + wrp;
            const float cx = g_cen[cen*3 + 0];
            const float cy = g_cen[cen*3 + 1];
            const float cz = g_cen[cen*3 + 2];
            const float* xb = x + (size_t)b * Nn * 3;
            int* outp = (int*)&sm[OIDXA + wrp*64];

            int count = 0;
            for (int base = 0; base < Nn && count < Kk; base += 32) {
                int p = base + lane;
                float qx = xb[p*3 + 0], qy = xb[p*3 + 1], qz = xb[p*3 + 2];
                float dx = __fsub_rn(cx, qx);
                float dy = __fsub_rn(cy, qy);
                float dz = __fsub_rn(cz, qz);
                float d  = __fadd_rn(__fadd_rn(__fmul_rn(dx,dx), __fmul_rn(dy,dy)),
                                     __fmul_rn(dz,dz));
                bool hit = d < 0.04f;
                unsigned m = __ballot_sync(0xffffffffu, hit);
                int rk = __popc(m & ((1u << lane) - 1u));
                if (hit && (count + rk) < Kk) outp[count + rk] = p;
                count += __popc(m);
            }
            count = min(count, Kk);
            for (int q = count + lane; q < Kk; q += 32) outp[q] = -1;
        }
        __syncthreads();

        const int cen = b * Ss + s0 + wgid;
        const int OF = OBUF + wgid * GRP;   // F [67][65]
        const int OH = OF + 67*65;          // H [64][65]
        int* sidx = (int*)&sm[OIDXA + wgid*64];

        // ---- gather: 4 warps per group, 16 ks per warp ----
        const float* xcb = xc + (size_t)b * Nn * 64;
        const float* xb  = x  + (size_t)b * Nn * 3;
        for (int kk = 0; kk < 16; kk++) {
            int k  = wg_warp * 16 + kk;
            int gi = sidx[k];
            gi = gi < 0 ? 0 : gi;
            const float* row = xcb + (size_t)gi * 64;
            sm[OF + lane*65 + k]      = row[lane];
            sm[OF + (lane+32)*65 + k] = row[lane + 32];
            if (lane < 3)
                sm[OF + (64+lane)*65 + k] = xb[gi*3 + lane] - g_cen[cen*3 + lane];
        }
        __syncthreads();

        float acc[8][4];

        // ---- layer 1: H = relu(W1f @ F + b1f) ----
#pragma unroll
        for (int i = 0; i < 8; i++)
#pragma unroll
            for (int j = 0; j < 4; j++) acc[i][j] = 0.f;
        for (int c = 0; c < 67; c++) {
            float fv[4];
#pragma unroll
            for (int j = 0; j < 4; j++) fv[j] = sm[OF + c*65 + tx*4 + j];
#pragma unroll
            for (int i = 0; i < 8; i++) {
                float wv = sm[OW1 + (ty*8 + i)*67 + c];
#pragma unroll
                for (int j = 0; j < 4; j++) acc[i][j] = fmaf(wv, fv[j], acc[i][j]);
            }
        }
#pragma unroll
        for (int i = 0; i < 8; i++) {
            float bia = sm[OB1 + ty*8 + i];
#pragma unroll
            for (int j = 0; j < 4; j++)
                sm[OH + (ty*8 + i)*65 + tx*4 + j] = fmaxf(acc[i][j] + bia, 0.f);
        }
        __syncthreads();

        // ---- layer 2 (into F buffer) ----
#pragma unroll
        for (int i = 0; i < 8; i++)
#pragma unroll
            for (int j = 0; j < 4; j++) acc[i][j] = 0.f;
        for (int c = 0; c < 64; c++) {
            float fv[4];
#pragma unroll
            for (int j = 0; j < 4; j++) fv[j] = sm[OH + c*65 + tx*4 + j];
#pragma unroll
            for (int i = 0; i < 8; i++) {
                float wv = sm[OW2 + (ty*8 + i)*65 + c];
#pragma unroll
                for (int j = 0; j < 4; j++) acc[i][j] = fmaf(wv, fv[j], acc[i][j]);
            }
        }
#pragma unroll
        for (int i = 0; i < 8; i++) {
            float bia = sm[OB2 + ty*8 + i];
#pragma unroll
            for (int j = 0; j < 4; j++)
                sm[OF + (ty*8 + i)*65 + tx*4 + j] = fmaxf(acc[i][j] + bia, 0.f);
        }
        __syncthreads();

        // ---- layer 3 (128 outs, two 64-row passes) + masked maxpool ----
        for (int op = 0; op < 2; op++) {
#pragma unroll
            for (int i = 0; i < 8; i++)
#pragma unroll
                for (int j = 0; j < 4; j++) acc[i][j] = 0.f;
            for (int c = 0; c < 64; c++) {
                float fv[4];
#pragma unroll
                for (int j = 0; j < 4; j++) fv[j] = sm[OF + c*65 + tx*4 + j];
#pragma unroll
                for (int i = 0; i < 8; i++) {
                    float wv = sm[OW3 + (op*64 + ty*8 + i)*65 + c];
#pragma unroll
                    for (int j = 0; j < 4; j++) acc[i][j] = fmaf(wv, fv[j], acc[i][j]);
                }
            }
#pragma unroll
            for (int i = 0; i < 8; i++) {
                int o = op*64 + ty*8 + i;
                float bia = sm[OB3 + o];
                float m = -INFINITY;
#pragma unroll
                for (int j = 0; j < 4; j++) {
                    int k = tx*4 + j;
                    float v = fmaxf(acc[i][j] + bia, 0.f);
                    if (sidx[k] >= 0) m = fmaxf(m, v);
                }
                // reduce across the 16 tx threads (contiguous 16-lane groups)
#pragma unroll
                for (int off = 8; off; off >>= 1)
                    m = fmaxf(m, __shfl_xor_sync(0xffffffffu, m, off, 16));
                if (tx == 0) pooled[(size_t)cen * 128 + o] = m;
            }
        }
    }
}

// ---------------- launch ----------------
extern "C" void kernel_launch(void* const* d_in, const int* in_sizes, int n_in,
                              void* d_out, int out_size)
{
    const float* x   = (const float*)d_in[0];
    const float* xc  = (const float*)d_in[1];
    WPtrs w;
    w.W1  = (const float*)d_in[2];
    w.b1  = (const float*)d_in[3];
    w.g1  = (const float*)d_in[4];
    w.bt1 = (const float*)d_in[5];
    w.m1  = (const float*)d_in[6];
    w.v1  = (const float*)d_in[7];
    w.W2  = (const float*)d_in[8];
    w.b2  = (const float*)d_in[9];
    w.g2  = (const float*)d_in[10];
    w.bt2 = (const float*)d_in[11];
    w.m2  = (const float*)d_in[12];
    w.v2  = (const float*)d_in[13];
    w.W3  = (const float*)d_in[14];
    w.b3  = (const float*)d_in[15];
    w.g3  = (const float*)d_in[16];
    w.bt3 = (const float*)d_in[17];
    w.m3  = (const float*)d_in[18];
    w.v3  = (const float*)d_in[19];
    float* out = (float*)d_out;

    sort_kernel<<<Bb, 1024>>>(x);

    cudaFuncSetAttribute(pipe_kernel, cudaFuncAttributeMaxDynamicSharedMemorySize, SMEM_BYTES);
    pipe_kernel<<<GRID, TPB, SMEM_BYTES>>>(x, xc, out, w);
}

// round 15
// speedup vs baseline: 1.1468x; 1.1468x over previous
#include <cuda_runtime.h>
#include <math.h>
#include <float.h>
#include <stdint.h>

#define Bb 4
#define Nn 8192
#define Ss 2048
#define Kk 64
#define EPSf 1e-5f

#define FCTAS 4                  // 1 FPS CTA per batch
#define WCTAS 144                // persistent worker CTAs
#define GRID  (FCTAS + WCTAS)    // 148 CTAs = 1/SM, single wave
#define TPB   512
#define NT    ((Bb*Ss)/4)        // worker tasks (4 centroids each)

typedef unsigned long long ull;

// ---------------- device scratch ----------------
__device__ float g_cen[Bb*Ss*3];
__device__ int   g_prog[Bb];
__device__ float g_sx[Bb*Nn];    // spatially sorted coords
__device__ float g_sy[Bb*Nn];
__device__ float g_sz[Bb*Nn];

// ---------------- packed f32x2 helpers (per-lane rn == scalar rn) ----------------
__device__ __forceinline__ ull pk2(float lo, float hi) {
    ull r; asm("mov.b64 %0, {%1, %2};" : "=l"(r) : "f"(lo), "f"(hi)); return r;
}
__device__ __forceinline__ void up2(ull v, float& a, float& b) {
    asm("mov.b64 {%0, %1}, %2;" : "=f"(a), "=f"(b) : "l"(v));
}
__device__ __forceinline__ ull add2(ull a, ull b) {
    ull r; asm("add.rn.f32x2 %0, %1, %2;" : "=l"(r) : "l"(a), "l"(b)); return r;
}
__device__ __forceinline__ ull mul2(ull a, ull b) {
    ull r; asm("mul.rn.f32x2 %0, %1, %2;" : "=l"(r) : "l"(a), "l"(b)); return r;
}

__device__ __forceinline__ int ld_acquire_gpu(const int* p) {
    int v; asm volatile("ld.acquire.gpu.global.s32 %0, [%1];" : "=r"(v) : "l"(p) : "memory");
    return v;
}
__device__ __forceinline__ void st_release_gpu(int* p, int v) {
    asm volatile("st.release.gpu.global.s32 [%0], %1;" :: "l"(p), "r"(v) : "memory");
}

// weight pointers, passed by value
struct WPtrs {
    const float *W1, *b1, *g1, *bt1, *m1, *v1;
    const float *W2, *b2, *g2, *bt2, *m2, *v2;
    const float *W3, *b3, *g3, *bt3, *m3, *v3;
};

// ---------------- spatial counting sort (Morton 8x8x8) + g_prog reset ----------------
__global__ void __launch_bounds__(1024) sort_kernel(const float* __restrict__ x)
{
    __shared__ int cnt[512];
    __shared__ int psum[512];
    const int b = blockIdx.x;
    const int tid = threadIdx.x;
    const float* xb = x + (size_t)b * Nn * 3;

    if (tid == 0) g_prog[b] = 0;
    if (tid < 512) cnt[tid] = 0;
    __syncthreads();

    int cid[8];
#pragma unroll
    for (int j = 0; j < 8; j++) {
        int p = tid * 8 + j;
        float px = xb[p*3 + 0], py = xb[p*3 + 1], pz = xb[p*3 + 2];
        int ix = min(7, max(0, (int)(px * 8.0f)));
        int iy = min(7, max(0, (int)(py * 8.0f)));
        int iz = min(7, max(0, (int)(pz * 8.0f)));
        int m = (ix & 1) | ((iy & 1) << 1) | ((iz & 1) << 2)
              | ((ix & 2) << 2) | ((iy & 2) << 3) | ((iz & 2) << 4)
              | ((ix & 4) << 4) | ((iy & 4) << 5) | ((iz & 4) << 6);
        cid[j] = m;
        atomicAdd(&cnt[m], 1);
    }
    __syncthreads();
    // Hillis-Steele exclusive scan over 512 counts
    if (tid < 512) psum[tid] = cnt[tid];
    __syncthreads();
    for (int off = 1; off < 512; off <<= 1) {
        int v = 0;
        if (tid < 512 && tid >= off) v = psum[tid - off];
        __syncthreads();
        if (tid < 512 && tid >= off) psum[tid] += v;
        __syncthreads();
    }
    if (tid < 512) { psum[tid] -= cnt[tid]; cnt[tid] = 0; }
    __syncthreads();
#pragma unroll
    for (int j = 0; j < 8; j++) {
        int p = tid * 8 + j;
        int pos = psum[cid[j]] + atomicAdd(&cnt[cid[j]], 1);
        g_sx[b*Nn + pos] = xb[p*3 + 0];
        g_sy[b*Nn + pos] = xb[p*3 + 1];
        g_sz[b*Nn + pos] = xb[p*3 + 2];
    }
}

// ---------------- shared-memory layout (floats) : worker view ----------------
#define OW1 0
#define OB1 (OW1 + 64*67)
#define OW2 (OB1 + 64)
#define OB2 (OW2 + 64*65)
#define OW3 (OB2 + 64)
#define OB3 (OW3 + 128*65)
#define OBUF (OB3 + 128)
#define GRP  (67*65 + 64*65)
#define OIDXA (OBUF + 4*GRP)
#define SMEM_FLOATS (OIDXA + 4*64)
#define SMEM_BYTES  (SMEM_FLOATS * 4)
// fps view (same dynamic buffer): sorted coords + packed combine slots
#define F_SX   0
#define F_SY   Nn
#define F_SZ   (2*Nn)
#define F_KEY  (3*Nn)            // [2][16] u64 (parity-buffered packed {val,idx})

// per-half sub-ball state
struct Half {
    float mx, my, mz;   // ball center
    float rr;           // conservative radius
    float T;            // prune threshold on |c-m|^2
    float bv;           // cached max dist in this half
    int   bj;           // cached best local j (global 0..15 index space)
};

// =====================================================================
// persistent kernel, single launch (512 threads everywhere):
//   CTA 0..3   : FPS, 512 thr x 16 pts, split-ball exact pruning
//   CTA 4..147 : workers (4 x 128-thread groups), consume via g_prog
// =====================================================================
__global__ void __launch_bounds__(TPB, 1)
pipe_kernel(const float* __restrict__ x, const float* __restrict__ xc,
            float* __restrict__ out, WPtrs w)
{
    extern __shared__ float sm[];
    const int tid  = threadIdx.x;
    const int lane = tid & 31;
    const int wrp  = tid >> 5;

    if (blockIdx.x < FCTAS) {
        // ================= FPS (512 threads, 16 sorted pts/thread) =================
        const int b = blockIdx.x;

        float* sxs = sm + F_SX;
        float* sys = sm + F_SY;
        float* szs = sm + F_SZ;
        ull* skeyA = (ull*)(sm + F_KEY);    // [2][16]

        for (int i = tid; i < Nn; i += TPB) {
            sxs[i] = g_sx[b*Nn + i];
            sys[i] = g_sy[b*Nn + i];
            szs[i] = g_sz[b*Nn + i];
        }

        // 16 sorted points per thread (8 packed pairs); static reg indexing only
        ull px[8], py[8], pz[8];
        float dist[16];
#pragma unroll
        for (int i = 0; i < 8; i++) {
            int p = b*Nn + tid * 16 + i * 2;
            px[i] = pk2(g_sx[p], g_sx[p+1]);
            py[i] = pk2(g_sy[p], g_sy[p+1]);
            pz[i] = pk2(g_sz[p], g_sz[p+1]);
        }
#pragma unroll
        for (int j = 0; j < 16; j++) dist[j] = 1e10f;

        // two 8-point sub-balls (halves h=0: i 0..3, h=1: i 4..7), conservative fp
        Half H[2];
#pragma unroll
        for (int h = 0; h < 2; h++) {
            float mx = 0.f, my = 0.f, mz = 0.f;
#pragma unroll
            for (int i = 0; i < 4; i++) {
                float a0, a1;
                up2(px[h*4+i], a0, a1); mx += a0 + a1;
                up2(py[h*4+i], a0, a1); my += a0 + a1;
                up2(pz[h*4+i], a0, a1); mz += a0 + a1;
            }
            mx *= 0.125f; my *= 0.125f; mz *= 0.125f;
            float r2 = 0.f;
#pragma unroll
            for (int i = 0; i < 4; i++) {
                float a0, a1, b0, b1, c0, c1;
                up2(px[h*4+i], a0, a1); up2(py[h*4+i], b0, b1); up2(pz[h*4+i], c0, c1);
                float dx0 = a0 - mx, dy0 = b0 - my, dz0 = c0 - mz;
                float dx1 = a1 - mx, dy1 = b1 - my, dz1 = c1 - mz;
                r2 = fmaxf(r2, dx0*dx0 + dy0*dy0 + dz0*dz0);
                r2 = fmaxf(r2, dx1*dx1 + dy1*dy1 + dz1*dz1);
            }
            H[h].mx = mx; H[h].my = my; H[h].mz = mz;
            H[h].rr = __fsqrt_rn(r2) * 1.0002f + 1e-7f;
            H[h].T  = 3.0e38f;   // force full path initially
            H[h].bv = 0.f;
            H[h].bj = h * 8;
        }

        // initial centroid = ORIGINAL point 0's coords
        const float* xb0 = x + (size_t)b * Nn * 3;
        float cx = xb0[0], cy = xb0[1], cz = xb0[2];

        int* progp = &g_prog[b];
        __syncthreads();   // staging done

        for (int s = 0; s < Ss; s++) {
            const int par = s & 1;
            if (tid == 0) {
                int oc = (b*Ss + s) * 3;
                g_cen[oc+0] = cx; g_cen[oc+1] = cy; g_cen[oc+2] = cz;
                out[oc+0]  = cx; out[oc+1]  = cy; out[oc+2]  = cz;
                if ((s & 7) == 7) st_release_gpu(progp, s + 1);
            }

            const ull ncx = pk2(-cx, -cx);
            const ull ncy = pk2(-cy, -cy);
            const ull ncz = pk2(-cz, -cz);

            // per-half exact prune + update
#pragma unroll
            for (int h = 0; h < 2; h++) {
                float ex = cx - H[h].mx, ey = cy - H[h].my, ez = cz - H[h].mz;
                float s2 = fmaf(ez, ez, fmaf(ey, ey, ex*ex));
                bool fullp = s2 < H[h].T;
                if (__any_sync(0xffffffffu, fullp)) {
                    if (fullp) {
                        float nbv = -1.0f;
                        int   nbj = h * 8;
#pragma unroll
                        for (int i = 0; i < 4; i++) {
                            int ii = h*4 + i;
                            ull dx = add2(px[ii], ncx);
                            ull dy = add2(py[ii], ncy);
                            ull dz = add2(pz[ii], ncz);
                            ull dd = add2(add2(mul2(dx,dx), mul2(dy,dy)), mul2(dz,dz));
                            float d0, d1; up2(dd, d0, d1);
                            float n0 = fminf(dist[2*ii],   d0);
                            float n1 = fminf(dist[2*ii+1], d1);
                            dist[2*ii] = n0; dist[2*ii+1] = n1;
                            float vp = fmaxf(n0, n1);
                            int   jp = (n0 >= n1) ? (2*ii) : (2*ii + 1); // tie -> lower j
                            if (vp > nbv) { nbv = vp; nbj = jp; }        // strict > keeps lower j
                        }
                        H[h].bv = nbv; H[h].bj = nbj;
                        float sq = __fsqrt_rn(nbv) * 1.0001f;
                        float t0 = (H[h].rr + sq) * 1.0001f;
                        H[h].T = t0 * t0;
                    }
                }
            }

            // merge halves: max dist, tie -> half0 (lower indices)
            float bv; int bj;
            if (H[0].bv >= H[1].bv) { bv = H[0].bv; bj = H[0].bj; }
            else                    { bv = H[1].bv; bj = H[1].bj; }

            // warp combine: max value, then min sorted index on ties
            unsigned mv   = __float_as_uint(bv);
            unsigned wmax = __reduce_max_sync(0xffffffffu, mv);
            unsigned cand = (mv == wmax) ? (unsigned)(tid*16 + bj) : 0xffffffffu;
            unsigned wmi  = __reduce_min_sync(0xffffffffu, cand);

            // one packed STS.64 per warp
            if (lane == 0)
                skeyA[par*16 + wrp] = ((ull)wmax << 32) | (ull)wmi;
            __syncthreads();   // single 16-warp barrier per step

            // every warp redundantly reduces the 16 warp results
            ull k = (lane < 16) ? skeyA[par*16 + lane] : 0ull;
            unsigned v  = (unsigned)(k >> 32);
            unsigned id = (lane < 16) ? (unsigned)k : 0xffffffffu;
            unsigned M  = __reduce_max_sync(0xffffffffu, v);
            unsigned cn = (v == M) ? id : 0xffffffffu;
            int cur = (int)__reduce_min_sync(0xffffffffu, cn);   // sorted index
            cx = sxs[cur]; cy = sys[cur]; cz = szs[cur];
        }
        return;
    }

    // ================= persistent worker: ball query + MLP (512 thr) =================
    const int widx_ = blockIdx.x - FCTAS;

    // stage FOLDED weights, computed directly from raw inputs
    for (int i = tid; i < 64*67; i += TPB) {
        int o = i / 67;
        sm[OW1 + i] = w.W1[i] * (w.g1[o] * rsqrtf(w.v1[o] + EPSf));
    }
    for (int i = tid; i < 64*64; i += TPB) {
        int o = i >> 6, c = i & 63;
        sm[OW2 + o*65 + c] = w.W2[i] * (w.g2[o] * rsqrtf(w.v2[o] + EPSf));
    }
    for (int i = tid; i < 128*64; i += TPB) {
        int o = i >> 6, c = i & 63;
        sm[OW3 + o*65 + c] = w.W3[i] * (w.g3[o] * rsqrtf(w.v3[o] + EPSf));
    }
    for (int i = tid; i < 64; i += TPB) {
        sm[OB1 + i] = (w.b1[i] - w.m1[i]) * (w.g1[i] * rsqrtf(w.v1[i] + EPSf)) + w.bt1[i];
        sm[OB2 + i] = (w.b2[i] - w.m2[i]) * (w.g2[i] * rsqrtf(w.v2[i] + EPSf)) + w.bt2[i];
    }
    for (int i = tid; i < 128; i += TPB)
        sm[OB3 + i] = (w.b3[i] - w.m3[i]) * (w.g3[i] * rsqrtf(w.v3[i] + EPSf)) + w.bt3[i];

    float* pooled = out + (size_t)Bb * Ss * 3;

    // 4 warpgroups of 128 threads; one centroid per group
    const int wgid    = tid >> 7;        // 0..3
    const int wg_tid  = tid & 127;
    const int tx      = wg_tid & 15;     // 4 k-cols each
    const int ty      = wg_tid >> 4;     // 8 out-rows each (0..7)
    const int wg_warp = (tid >> 5) & 3;

    for (int t = widx_; t < NT; t += WCTAS) {
        const int b  = t & 3;
        const int s0 = (t >> 2) * 4;

        if (tid == 0) {
            while (ld_acquire_gpu(&g_prog[b]) < s0 + 4) __nanosleep(128);
        }
        __syncthreads();   // progress visible + previous task's buffers free

        // ---- ball query: warps 0..3, one centroid each ----
        if (wrp < 4) {
            const int cen = b * Ss + s0 + wrp;
            const float cx = g_cen[cen*3 + 0];
            const float cy = g_cen[cen*3 + 1];
            const float cz = g_cen[cen*3 + 2];
            const float* xb = x + (size_t)b * Nn * 3;
            int* outp = (int*)&sm[OIDXA + wrp*64];

            int count = 0;
            for (int base = 0; base < Nn && count < Kk; base += 32) {
                int p = base + lane;
                float qx = xb[p*3 + 0], qy = xb[p*3 + 1], qz = xb[p*3 + 2];
                float dx = __fsub_rn(cx, qx);
                float dy = __fsub_rn(cy, qy);
                float dz = __fsub_rn(cz, qz);
                float d  = __fadd_rn(__fadd_rn(__fmul_rn(dx,dx), __fmul_rn(dy,dy)),
                                     __fmul_rn(dz,dz));
                bool hit = d < 0.04f;
                unsigned m = __ballot_sync(0xffffffffu, hit);
                int rk = __popc(m & ((1u << lane) - 1u));
                if (hit && (count + rk) < Kk) outp[count + rk] = p;
                count += __popc(m);
            }
            count = min(count, Kk);
            for (int q = count + lane; q < Kk; q += 32) outp[q] = -1;
        }
        __syncthreads();

        const int cen = b * Ss + s0 + wgid;
        const int OF = OBUF + wgid * GRP;   // F [67][65]
        const int OH = OF + 67*65;          // H [64][65]
        int* sidx = (int*)&sm[OIDXA + wgid*64];

        // ---- gather: 4 warps per group, 16 ks per warp ----
        const float* xcb = xc + (size_t)b * Nn * 64;
        const float* xb  = x  + (size_t)b * Nn * 3;
        for (int kk = 0; kk < 16; kk++) {
            int k  = wg_warp * 16 + kk;
            int gi = sidx[k];
            gi = gi < 0 ? 0 : gi;
            const float* row = xcb + (size_t)gi * 64;
            sm[OF + lane*65 + k]      = row[lane];
            sm[OF + (lane+32)*65 + k] = row[lane + 32];
            if (lane < 3)
                sm[OF + (64+lane)*65 + k] = xb[gi*3 + lane] - g_cen[cen*3 + lane];
        }
        __syncthreads();

        float acc[8][4];

        // ---- layer 1: H = relu(W1f @ F + b1f) ----
#pragma unroll
        for (int i = 0; i < 8; i++)
#pragma unroll
            for (int j = 0; j < 4; j++) acc[i][j] = 0.f;
        for (int c = 0; c < 67; c++) {
            float fv[4];
#pragma unroll
            for (int j = 0; j < 4; j++) fv[j] = sm[OF + c*65 + tx*4 + j];
#pragma unroll
            for (int i = 0; i < 8; i++) {
                float wv = sm[OW1 + (ty*8 + i)*67 + c];
#pragma unroll
                for (int j = 0; j < 4; j++) acc[i][j] = fmaf(wv, fv[j], acc[i][j]);
            }
        }
#pragma unroll
        for (int i = 0; i < 8; i++) {
            float bia = sm[OB1 + ty*8 + i];
#pragma unroll
            for (int j = 0; j < 4; j++)
                sm[OH + (ty*8 + i)*65 + tx*4 + j] = fmaxf(acc[i][j] + bia, 0.f);
        }
        __syncthreads();

        // ---- layer 2 (into F buffer) ----
#pragma unroll
        for (int i = 0; i < 8; i++)
#pragma unroll
            for (int j = 0; j < 4; j++) acc[i][j] = 0.f;
        for (int c = 0; c < 64; c++) {
            float fv[4];
#pragma unroll
            for (int j = 0; j < 4; j++) fv[j] = sm[OH + c*65 + tx*4 + j];
#pragma unroll
            for (int i = 0; i < 8; i++) {
                float wv = sm[OW2 + (ty*8 + i)*65 + c];
#pragma unroll
                for (int j = 0; j < 4; j++) acc[i][j] = fmaf(wv, fv[j], acc[i][j]);
            }
        }
#pragma unroll
        for (int i = 0; i < 8; i++) {
            float bia = sm[OB2 + ty*8 + i];
#pragma unroll
            for (int j = 0; j < 4; j++)
                sm[OF + (ty*8 + i)*65 + tx*4 + j] = fmaxf(acc[i][j] + bia, 0.f);
        }
        __syncthreads();

        // ---- layer 3 (128 outs, two 64-row passes) + masked maxpool ----
        for (int op = 0; op < 2; op++) {
#pragma unroll
            for (int i = 0; i < 8; i++)
#pragma unroll
                for (int j = 0; j < 4; j++) acc[i][j] = 0.f;
            for (int c = 0; c < 64; c++) {
                float fv[4];
#pragma unroll
                for (int j = 0; j < 4; j++) fv[j] = sm[OF + c*65 + tx*4 + j];
#pragma unroll
                for (int i = 0; i < 8; i++) {
                    float wv = sm[OW3 + (op*64 + ty*8 + i)*65 + c];
#pragma unroll
                    for (int j = 0; j < 4; j++) acc[i][j] = fmaf(wv, fv[j], acc[i][j]);
                }
            }
#pragma unroll
            for (int i = 0; i < 8; i++) {
                int o = op*64 + ty*8 + i;
                float bia = sm[OB3 + o];
                float m = -INFINITY;
#pragma unroll
                for (int j = 0; j < 4; j++) {
                    int k = tx*4 + j;
                    float v = fmaxf(acc[i][j] + bia, 0.f);
                    if (sidx[k] >= 0) m = fmaxf(m, v);
                }
                // reduce across the 16 tx threads (contiguous 16-lane groups)
#pragma unroll
                for (int off = 8; off; off >>= 1)
                    m = fmaxf(m, __shfl_xor_sync(0xffffffffu, m, off, 16));
                if (tx == 0) pooled[(size_t)cen * 128 + o] = m;
            }
        }
    }
}

// ---------------- launch ----------------
extern "C" void kernel_launch(void* const* d_in, const int* in_sizes, int n_in,
                              void* d_out, int out_size)
{
    const float* x   = (const float*)d_in[0];
    const float* xc  = (const float*)d_in[1];
    WPtrs w;
    w.W1  = (const float*)d_in[2];
    w.b1  = (const float*)d_in[3];
    w.g1  = (const float*)d_in[4];
    w.bt1 = (const float*)d_in[5];
    w.m1  = (const float*)d_in[6];
    w.v1  = (const float*)d_in[7];
    w.W2  = (const float*)d_in[8];
    w.b2  = (const float*)d_in[9];
    w.g2  = (const float*)d_in[10];
    w.bt2 = (const float*)d_in[11];
    w.m2  = (const float*)d_in[12];
    w.v2  = (const float*)d_in[13];
    w.W3  = (const float*)d_in[14];
    w.b3  = (const float*)d_in[15];
    w.g3  = (const float*)d_in[16];
    w.bt3 = (const float*)d_in[17];
    w.m3  = (const float*)d_in[18];
    w.v3  = (const float*)d_in[19];
    float* out = (float*)d_out;

    sort_kernel<<<Bb, 1024>>>(x);

    cudaFuncSetAttribute(pipe_kernel, cudaFuncAttributeMaxDynamicSharedMemorySize, SMEM_BYTES);
    pipe_kernel<<<GRID, TPB, SMEM_BYTES>>>(x, xc, out, w);
}